// round 6
// baseline (speedup 1.0000x reference)
#include <cuda_runtime.h>
#include <cuda_bf16.h>
#include <cstdint>
#include <cstddef>

using bf16 = __nv_bfloat16;
using bf162 = __nv_bfloat162;

constexpr int Bdim = 8, Ldim = 512, Hdim = 768, Odim = 12;
constexpr int Kdim = Hdim;
constexpr float NEGC = 1000000000000.0f;

// CTA 128x128, warp tile 64x32 (8 warps: 2M x 4N), BK=64 elems, S=2 stages
constexpr int BM = 128, BN = 128, BK = 64;
constexpr int LDSE = 72;                       // 64 + 8 pad elems -> 144B stride (16B mult.)
constexpr int S = 2;
constexpr int KT = Kdim / BK;                  // 12
constexpr int STAGE_E = BM * LDSE;             // elems per operand stage
constexpr int STAGE_B = STAGE_E * 2;           // 18432 B
constexpr unsigned SMEM_DYN = 2u * S * STAGE_B;  // 73728 B

// ---------------- scratch ----------------------------------------------------
__device__ __align__(16) bf16 g_in [Bdim * Ldim * Hdim];
__device__ __align__(16) bf16 g_w1t[Odim * Hdim * Hdim];
__device__ __align__(16) bf16 g_U  [(size_t)Bdim * Odim * Ldim * Hdim];
__device__ float g_lina[Bdim * Ldim * Odim];
__device__ float g_linb[Bdim * Ldim * Odim];

// ---------------- helpers -----------------------------------------------------
__device__ __forceinline__ uint32_t s2u(const void* p) {
    return (uint32_t)__cvta_generic_to_shared(p);
}
__device__ __forceinline__ void cp16(uint32_t s, const void* g) {
    asm volatile("cp.async.cg.shared.global [%0], [%1], 16;" :: "r"(s), "l"(g));
}
__device__ __forceinline__ void cp_commit() {
    asm volatile("cp.async.commit_group;");
}
template <int N>
__device__ __forceinline__ void cp_wait() {
    asm volatile("cp.async.wait_group %0;" :: "n"(N));
}
__device__ __forceinline__ void mma_op(float* c, const uint32_t* a, const uint32_t* bq) {
    asm volatile(
        "mma.sync.aligned.m16n8k16.row.col.f32.bf16.bf16.f32 "
        "{%0,%1,%2,%3},{%4,%5,%6,%7},{%8,%9},{%0,%1,%2,%3};"
        : "+f"(c[0]), "+f"(c[1]), "+f"(c[2]), "+f"(c[3])
        : "r"(a[0]), "r"(a[1]), "r"(a[2]), "r"(a[3]), "r"(bq[0]), "r"(bq[1]));
}
__device__ __forceinline__ void ldsm4(uint32_t* d, uint32_t addr) {
    asm volatile("ldmatrix.sync.aligned.m8n8.x4.shared.b16 {%0,%1,%2,%3}, [%4];"
                 : "=r"(d[0]), "=r"(d[1]), "=r"(d[2]), "=r"(d[3]) : "r"(addr));
}

// Load one kk-group's fragments. aAddr/bAddr are lane-resolved smem byte addrs at kk=0.
__device__ __forceinline__ void load_frags(uint32_t aAddr, uint32_t bAddr, int kk,
                                           uint32_t fa[4][4], uint32_t fb[4][2]) {
    #pragma unroll
    for (int mt = 0; mt < 4; mt++)
        ldsm4(fa[mt], aAddr + mt * (16 * LDSE * 2) + kk * 2);
    #pragma unroll
    for (int p = 0; p < 2; p++) {
        uint32_t v[4];
        ldsm4(v, bAddr + p * (16 * LDSE * 2) + kk * 2);
        fb[2 * p][0] = v[0];     fb[2 * p][1] = v[1];
        fb[2 * p + 1][0] = v[2]; fb[2 * p + 1][1] = v[3];
    }
}

// 128x128x768 NT-GEMM mainloop, fragment-double-buffered
__device__ __forceinline__ void gemm_mainloop(const bf16* __restrict__ Ablk,
                                              const bf16* __restrict__ Bblk,
                                              float acc[4][4][4], char* smem) {
    int t = threadIdx.x;
    int lane = t & 31, warp = t >> 5;
    int wm = warp >> 2, wn = warp & 3;
    int r = lane & 7, sub = lane >> 3;

    bf16* Asm = reinterpret_cast<bf16*>(smem);
    bf16* Bsm = reinterpret_cast<bf16*>(smem + S * STAGE_B);

    // loader geometry: thread handles one full 128B row of one operand
    int lrow = t & 127;
    const bf16* gsrc = (t < 128 ? Ablk : Bblk) + (size_t)lrow * Kdim;
    uint32_t sdst = s2u((t < 128 ? Asm : Bsm) + lrow * LDSE);

    auto load_stage = [&](int kt, int st) {
        uint32_t d = sdst + st * STAGE_B;
        const bf16* g = gsrc + kt * BK;
        #pragma unroll
        for (int c = 0; c < 8; c++) cp16(d + c * 16, g + c * 8);
        cp_commit();
    };

    // consumer lane-resolved base addresses (kk=0, stage 0)
    uint32_t aAddr0 = s2u(Asm + (wm * 64 + (sub & 1) * 8 + r) * LDSE + (sub >> 1) * 8);
    uint32_t bAddr0 = s2u(Bsm + (wn * 32 + (sub >> 1) * 8 + r) * LDSE + (sub & 1) * 8);

    load_stage(0, 0);

    uint32_t fa[2][4][4], fb[2][4][2];

    #pragma unroll 1
    for (int kt = 0; kt < KT; kt++) {
        cp_wait<0>();
        __syncthreads();
        if (kt + 1 < KT) load_stage(kt + 1, (kt + 1) & 1);
        int st = kt & 1;
        uint32_t aAddr = aAddr0 + st * STAGE_B;
        uint32_t bAddr = bAddr0 + st * STAGE_B;

        load_frags(aAddr, bAddr, 0, fa[0], fb[0]);
        #pragma unroll
        for (int g = 0; g < 4; g++) {
            int cur = g & 1;
            if (g < 3) load_frags(aAddr, bAddr, (g + 1) * 16, fa[cur ^ 1], fb[cur ^ 1]);
            #pragma unroll
            for (int mt = 0; mt < 4; mt++)
                #pragma unroll
                for (int nt = 0; nt < 4; nt++)
                    mma_op(acc[mt][nt], fa[cur][mt], fb[cur][nt]);
        }
    }
}

// ---------------- prep kernels ------------------------------------------------
__global__ void convert_in_kernel(const float* __restrict__ in) {
    int i = (blockIdx.x * blockDim.x + threadIdx.x) * 4;
    float4 v = *reinterpret_cast<const float4*>(in + i);
    *reinterpret_cast<bf162*>(&g_in[i])     = __floats2bfloat162_rn(v.x, v.y);
    *reinterpret_cast<bf162*>(&g_in[i + 2]) = __floats2bfloat162_rn(v.z, v.w);
}

__global__ void transpose_w1_kernel(const float* __restrict__ w1) {
    __shared__ float tile[32][33];
    int n0 = blockIdx.x * 32, i0 = blockIdx.y * 32;
    int tx = threadIdx.x, ty = threadIdx.y;
    #pragma unroll
    for (int k = 0; k < 32; k += 8)
        tile[ty + k][tx] = w1[(size_t)(i0 + ty + k) * (Odim * Hdim) + n0 + tx];
    __syncthreads();
    #pragma unroll
    for (int k = 0; k < 32; k += 8)
        g_w1t[(size_t)(n0 + ty + k) * Hdim + i0 + tx] = __float2bfloat16(tile[tx][ty + k]);
}

__global__ void lin_kernel(const float* __restrict__ in, const float* __restrict__ w2) {
    int row = blockIdx.x;
    int o = threadIdx.x >> 5, lane = threadIdx.x & 31;
    const float* x = in + (size_t)row * Hdim;
    float sa = 0.f, sb = 0.f;
    for (int i = lane; i < Hdim; i += 32) {
        float v = x[i];
        sa += v * w2[i * Odim + o];
        sb += v * w2[(Hdim + i) * Odim + o];
    }
    #pragma unroll
    for (int off = 16; off; off >>= 1) {
        sa += __shfl_xor_sync(0xffffffffu, sa, off);
        sb += __shfl_xor_sync(0xffffffffu, sb, off);
    }
    if (lane == 0) { g_lina[row * Odim + o] = sa; g_linb[row * Odim + o] = sb; }
}

// ---------------- GEMM 1: U = in @ W1t^T (M=4096, N=9216, K=768) -------------
__global__ __launch_bounds__(256, 2) void gemm1_kernel() {
    extern __shared__ char smem[];
    const bf16* Ablk = g_in  + (size_t)blockIdx.y * BM * Kdim;
    const bf16* Bblk = g_w1t + (size_t)blockIdx.x * BN * Kdim;
    float acc[4][4][4];
    #pragma unroll
    for (int i = 0; i < 4; i++)
        #pragma unroll
        for (int j = 0; j < 4; j++)
            #pragma unroll
            for (int e = 0; e < 4; e++) acc[i][j][e] = 0.f;
    gemm_mainloop(Ablk, Bblk, acc, smem);

    int t = threadIdx.x, lane = t & 31, warp = t >> 5;
    int wm = warp >> 2, wn = warp & 3;
    int g = lane >> 2, tig = lane & 3;
    int o  = (blockIdx.x * BN) / Hdim;
    int jb = blockIdx.x * BN - o * Hdim;
    #pragma unroll
    for (int mt = 0; mt < 4; mt++) {
        int R = blockIdx.y * BM + wm * 64 + mt * 16 + g;
        int b = R >> 9, x = R & (Ldim - 1);
        #pragma unroll
        for (int nt = 0; nt < 4; nt++) {
            int j = jb + wn * 32 + nt * 8 + 2 * tig;
            size_t base = ((size_t)(b * Odim + o) * Ldim + x) * Hdim + j;
            *reinterpret_cast<bf162*>(&g_U[base]) =
                __floats2bfloat162_rn(acc[mt][nt][0], acc[mt][nt][1]);
            *reinterpret_cast<bf162*>(&g_U[base + (size_t)8 * Hdim]) =
                __floats2bfloat162_rn(acc[mt][nt][2], acc[mt][nt][3]);
        }
    }
}

// ------- GEMM 2 + fused epilogue ---------------------------------------------
__global__ __launch_bounds__(256, 2) void gemm2_kernel(const float* __restrict__ w2,
                                                       const int* __restrict__ mask,
                                                       float* __restrict__ out) {
    extern __shared__ char smem[];
    __shared__ int   rowm[BM];
    __shared__ float rowv[BM];
    __shared__ int   colm[BN];
    __shared__ float colv[BN];

    int z = blockIdx.z;
    int b = z / Odim, o = z - b * Odim;
    const bf16* Ablk = g_U  + ((size_t)z * Ldim + blockIdx.y * BM) * Kdim;
    const bf16* Bblk = g_in + ((size_t)b * Ldim + blockIdx.x * BN) * Kdim;
    float acc[4][4][4];
    #pragma unroll
    for (int i = 0; i < 4; i++)
        #pragma unroll
        for (int j = 0; j < 4; j++)
            #pragma unroll
            for (int e = 0; e < 4; e++) acc[i][j][e] = 0.f;
    gemm_mainloop(Ablk, Bblk, acc, smem);

    int t = threadIdx.x, lane = t & 31, warp = t >> 5;
    int wm = warp >> 2, wn = warp & 3;
    int g = lane >> 2, tig = lane & 3;
    float bias = w2[2 * Hdim * Odim + o];
    if (t < BM) {
        int x = blockIdx.y * BM + t;
        rowm[t] = mask[b * Ldim + x];
        rowv[t] = g_lina[(b * Ldim + x) * Odim + o] + bias;
        int y = blockIdx.x * BN + t;
        colm[t] = mask[b * Ldim + y];
        colv[t] = g_linb[(b * Ldim + y) * Odim + o];
    }
    __syncthreads();

    #pragma unroll
    for (int mt = 0; mt < 4; mt++) {
        #pragma unroll
        for (int h = 0; h < 2; h++) {
            int rl = wm * 64 + mt * 16 + g + h * 8;
            int x = blockIdx.y * BM + rl;
            int rm = rowm[rl];
            float rv = rowv[rl];
            float* orow = out + ((size_t)z * Ldim + x) * Ldim + blockIdx.x * BN;
            #pragma unroll
            for (int nt = 0; nt < 4; nt++) {
                int cl = wn * 32 + nt * 8 + 2 * tig;
                int y = blockIdx.x * BN + cl;
                float2 v;
                v.x = (rm && colm[cl])     ? (acc[mt][nt][h * 2]     + rv + colv[cl])     : -NEGC;
                v.y = (rm && colm[cl + 1]) ? (acc[mt][nt][h * 2 + 1] + rv + colv[cl + 1]) : -NEGC;
                if (y     < x) v.x -= NEGC;
                if (y + 1 < x) v.y -= NEGC;
                *reinterpret_cast<float2*>(orow + cl) = v;
            }
        }
    }
}

// ---------------- launch ------------------------------------------------------
extern "C" void kernel_launch(void* const* d_in, const int* in_sizes, int n_in,
                              void* d_out, int out_size) {
    (void)out_size;
    const float* inputs = nullptr; const float* w1 = nullptr;
    const float* w2 = nullptr;     const int* mask = nullptr;
    for (int i = 0; i < n_in; i++) {
        int s = in_sizes[i];
        if      (s == Bdim * Ldim * Hdim)    inputs = (const float*)d_in[i];
        else if (s == Hdim * Odim * Hdim)    w1     = (const float*)d_in[i];
        else if (s == (2 * Hdim + 1) * Odim) w2     = (const float*)d_in[i];
        else if (s == Bdim * Ldim)           mask   = (const int*)d_in[i];
    }
    float* out = (float*)d_out;

    cudaFuncSetAttribute(gemm1_kernel, cudaFuncAttributeMaxDynamicSharedMemorySize, SMEM_DYN);
    cudaFuncSetAttribute(gemm2_kernel, cudaFuncAttributeMaxDynamicSharedMemorySize, SMEM_DYN);

    convert_in_kernel<<<(Bdim * Ldim * Hdim) / 1024, 256>>>(inputs);
    transpose_w1_kernel<<<dim3((Odim * Hdim) / 32, Hdim / 32), dim3(32, 8)>>>(w1);
    lin_kernel<<<Bdim * Ldim, 384>>>(inputs, w2);
    gemm1_kernel<<<dim3((Odim * Hdim) / BN, (Bdim * Ldim) / BM), 256, SMEM_DYN>>>();
    gemm2_kernel<<<dim3(Ldim / BN, Ldim / BM, Bdim * Odim), 256, SMEM_DYN>>>(w2, mask, out);
}

// round 7
// speedup vs baseline: 1.6743x; 1.6743x over previous
#include <cuda_runtime.h>
#include <cuda_bf16.h>
#include <cstdint>
#include <cstddef>

using bf16 = __nv_bfloat16;
using bf162 = __nv_bfloat162;

constexpr int Bdim = 8, Ldim = 512, Hdim = 768, Odim = 12;
constexpr int Kdim = Hdim;
constexpr float NEGC = 1000000000000.0f;

constexpr int BM = 128, BN = 128, BK = 32, PAD = 8, LDSH = BK + PAD; // 40
constexpr int BUFBYTES = BM * LDSH * 2;    // 10240 bytes per stage buffer

// ---------------- scratch ----------------------------------------------------
__device__ __align__(16) bf16 g_in [Bdim * Ldim * Hdim];               // all rows, bf16
__device__ __align__(16) bf16 g_inc[Bdim * Ldim * Hdim];               // compacted live rows
__device__ __align__(16) bf16 g_U  [(size_t)Bdim * Odim * Ldim * Hdim]; // compacted per (b,o)
__device__ __align__(16) bf16 g_w1t[Odim * Hdim * Hdim];
__device__ float g_lina[Bdim * Ldim * Odim];
__device__ float g_linb[Bdim * Ldim * Odim];
__device__ int   g_idx [Bdim * Ldim];      // live-row original indices per batch
__device__ int   g_nb  [Bdim];             // live-row counts

// ---------------- helpers -----------------------------------------------------
__device__ __forceinline__ uint32_t s2u(const void* p) {
    return (uint32_t)__cvta_generic_to_shared(p);
}
__device__ __forceinline__ void cp16(uint32_t s, const void* g) {
    asm volatile("cp.async.cg.shared.global [%0], [%1], 16;" :: "r"(s), "l"(g));
}
__device__ __forceinline__ void cp_commit() {
    asm volatile("cp.async.commit_group;");
}
template <int N>
__device__ __forceinline__ void cp_wait() {
    asm volatile("cp.async.wait_group %0;" :: "n"(N));
}
__device__ __forceinline__ void mma_op(float* c, const uint32_t* a, const uint32_t* bq) {
    asm volatile(
        "mma.sync.aligned.m16n8k16.row.col.f32.bf16.bf16.f32 "
        "{%0,%1,%2,%3},{%4,%5,%6,%7},{%8,%9},{%0,%1,%2,%3};"
        : "+f"(c[0]), "+f"(c[1]), "+f"(c[2]), "+f"(c[3])
        : "r"(a[0]), "r"(a[1]), "r"(a[2]), "r"(a[3]), "r"(bq[0]), "r"(bq[1]));
}

// R1-proven: one BK=32 slab, warp tile 64x32
__device__ __forceinline__ void mma_tile(float acc[4][4][4],
                                         const bf16 (*As)[LDSH],
                                         const bf16 (*Bs)[LDSH],
                                         int wm, int wn, int lane) {
    int r = lane & 7, sub = lane >> 3;
    #pragma unroll
    for (int kk = 0; kk < BK; kk += 16) {
        uint32_t a[4][4], bq[4][2];
        #pragma unroll
        for (int mt = 0; mt < 4; mt++) {
            uint32_t addr = s2u(&As[wm * 64 + mt * 16 + (sub & 1) * 8 + r][kk + (sub >> 1) * 8]);
            asm volatile("ldmatrix.sync.aligned.m8n8.x4.shared.b16 {%0,%1,%2,%3}, [%4];"
                         : "=r"(a[mt][0]), "=r"(a[mt][1]), "=r"(a[mt][2]), "=r"(a[mt][3])
                         : "r"(addr));
        }
        #pragma unroll
        for (int p = 0; p < 2; p++) {
            uint32_t addr = s2u(&Bs[wn * 32 + p * 16 + (sub >> 1) * 8 + r][kk + (sub & 1) * 8]);
            uint32_t v0, v1, v2, v3;
            asm volatile("ldmatrix.sync.aligned.m8n8.x4.shared.b16 {%0,%1,%2,%3}, [%4];"
                         : "=r"(v0), "=r"(v1), "=r"(v2), "=r"(v3) : "r"(addr));
            bq[2 * p][0] = v0; bq[2 * p][1] = v1;
            bq[2 * p + 1][0] = v2; bq[2 * p + 1][1] = v3;
        }
        #pragma unroll
        for (int mt = 0; mt < 4; mt++)
            #pragma unroll
            for (int nt = 0; nt < 4; nt++)
                mma_op(acc[mt][nt], a[mt], bq[nt]);
    }
}

// R1-proven 128x128x768 NT-GEMM mainloop
__device__ __forceinline__ void gemm_mainloop(const bf16* __restrict__ Ablk,
                                              const bf16* __restrict__ Bblk,
                                              float acc[4][4][4]) {
    __shared__ __align__(16) bf16 As[2][BM][LDSH];
    __shared__ __align__(16) bf16 Bs[2][BM][LDSH];
    int t = threadIdx.x;
    int lane = t & 31, warp = t >> 5;
    int wm = warp >> 2, wn = warp & 3;
    int kc = t & 3, r0 = t >> 2;

    const bf16* ag0 = Ablk + (size_t)r0 * Kdim + kc * 8;
    const bf16* ag1 = ag0 + (size_t)64 * Kdim;
    const bf16* bg0 = Bblk + (size_t)r0 * Kdim + kc * 8;
    const bf16* bg1 = bg0 + (size_t)64 * Kdim;
    uint32_t sa0 = s2u(&As[0][r0][kc * 8]);
    uint32_t sa1 = s2u(&As[0][r0 + 64][kc * 8]);
    uint32_t sb0 = s2u(&Bs[0][r0][kc * 8]);
    uint32_t sb1 = s2u(&Bs[0][r0 + 64][kc * 8]);

    cp16(sa0, ag0); cp16(sa1, ag1); cp16(sb0, bg0); cp16(sb1, bg1);
    cp_commit();

    constexpr int KT = Kdim / BK;  // 24
    #pragma unroll 1
    for (int kt = 0; kt < KT; kt++) {
        int buf = kt & 1;
        if (kt + 1 < KT) {
            int nb = buf ^ 1;
            int koff = (kt + 1) * BK;
            cp16(sa0 + nb * BUFBYTES, ag0 + koff);
            cp16(sa1 + nb * BUFBYTES, ag1 + koff);
            cp16(sb0 + nb * BUFBYTES, bg0 + koff);
            cp16(sb1 + nb * BUFBYTES, bg1 + koff);
            cp_commit();
            cp_wait<1>();
        } else {
            cp_wait<0>();
        }
        __syncthreads();
        mma_tile(acc, As[buf], Bs[buf], wm, wn, lane);
        __syncthreads();
    }
}

// ---------------- prep kernels ------------------------------------------------
__global__ void convert_in_kernel(const float* __restrict__ in) {
    int i = (blockIdx.x * blockDim.x + threadIdx.x) * 4;
    float4 v = *reinterpret_cast<const float4*>(in + i);
    *reinterpret_cast<bf162*>(&g_in[i])     = __floats2bfloat162_rn(v.x, v.y);
    *reinterpret_cast<bf162*>(&g_in[i + 2]) = __floats2bfloat162_rn(v.z, v.w);
}

__global__ void transpose_w1_kernel(const float* __restrict__ w1) {
    __shared__ float tile[32][33];
    int n0 = blockIdx.x * 32, i0 = blockIdx.y * 32;
    int tx = threadIdx.x, ty = threadIdx.y;
    #pragma unroll
    for (int k = 0; k < 32; k += 8)
        tile[ty + k][tx] = w1[(size_t)(i0 + ty + k) * (Odim * Hdim) + n0 + tx];
    __syncthreads();
    #pragma unroll
    for (int k = 0; k < 32; k += 8)
        g_w1t[(size_t)(n0 + ty + k) * Hdim + i0 + tx] = __float2bfloat16(tile[tx][ty + k]);
}

__global__ void lin_kernel(const float* __restrict__ in, const float* __restrict__ w2) {
    int row = blockIdx.x;
    int o = threadIdx.x >> 5, lane = threadIdx.x & 31;
    const float* x = in + (size_t)row * Hdim;
    float sa = 0.f, sb = 0.f;
    for (int i = lane; i < Hdim; i += 32) {
        float v = x[i];
        sa += v * w2[i * Odim + o];
        sb += v * w2[(Hdim + i) * Odim + o];
    }
    #pragma unroll
    for (int off = 16; off; off >>= 1) {
        sa += __shfl_xor_sync(0xffffffffu, sa, off);
        sb += __shfl_xor_sync(0xffffffffu, sb, off);
    }
    if (lane == 0) { g_lina[row * Odim + o] = sa; g_linb[row * Odim + o] = sb; }
}

// mask prefix-scan: one block per batch, builds idx list + count
__global__ void scan_kernel(const int* __restrict__ mask) {
    __shared__ int temp[Ldim];
    int b = blockIdx.x, t = threadIdx.x;
    int m = mask[b * Ldim + t];
    temp[t] = m;
    __syncthreads();
    for (int off = 1; off < Ldim; off <<= 1) {
        int v = temp[t];
        int add = (t >= off) ? temp[t - off] : 0;
        __syncthreads();
        temp[t] = v + add;
        __syncthreads();
    }
    if (m) g_idx[b * Ldim + temp[t] - 1] = t;
    if (t == Ldim - 1) g_nb[b] = temp[t];
}

// gather live input rows into contiguous g_inc
__global__ void compact_kernel() {
    int rb = blockIdx.x;
    int b = rb >> 9, r = rb & (Ldim - 1);
    if (r >= g_nb[b]) return;
    int src = g_idx[b * Ldim + r];
    const uint4* s = reinterpret_cast<const uint4*>(&g_in[((size_t)b * Ldim + src) * Hdim]);
    uint4* d = reinterpret_cast<uint4*>(&g_inc[((size_t)b * Ldim + r) * Hdim]);
    int t = threadIdx.x;
    if (t < 96) d[t] = s[t];   // 96 * 16B = 1536B = 768 bf16
}

// flood fill: dead value = -NEG - tril*NEG (overwritten later at live positions)
__global__ void fill_kernel(float* __restrict__ out) {
    int f4 = blockIdx.x * blockDim.x + threadIdx.x;
    int y4 = (f4 & 127) << 2;
    int x  = (f4 >> 7) & (Ldim - 1);
    float4 v;
    v.x = (y4     < x) ? -2.0f * NEGC : -NEGC;
    v.y = (y4 + 1 < x) ? -2.0f * NEGC : -NEGC;
    v.z = (y4 + 2 < x) ? -2.0f * NEGC : -NEGC;
    v.w = (y4 + 3 < x) ? -2.0f * NEGC : -NEGC;
    reinterpret_cast<float4*>(out)[f4] = v;
}

// ---------------- GEMM 1 on compacted rows -----------------------------------
__global__ __launch_bounds__(256) void gemm1_kernel() {
    int b = blockIdx.y >> 2, mtile = blockIdx.y & 3;
    int nb = g_nb[b];
    if (mtile * BM >= nb) return;

    const bf16* Ablk = g_inc + ((size_t)b * Ldim + mtile * BM) * Kdim;
    const bf16* Bblk = g_w1t + (size_t)blockIdx.x * BN * Kdim;
    float acc[4][4][4];
    #pragma unroll
    for (int i = 0; i < 4; i++)
        #pragma unroll
        for (int j = 0; j < 4; j++)
            #pragma unroll
            for (int e = 0; e < 4; e++) acc[i][j][e] = 0.f;
    gemm_mainloop(Ablk, Bblk, acc);

    int t = threadIdx.x, lane = t & 31, warp = t >> 5;
    int wm = warp >> 2, wn = warp & 3;
    int g = lane >> 2, tig = lane & 3;
    int o  = (blockIdx.x * BN) / Hdim;
    int jb = blockIdx.x * BN - o * Hdim;
    #pragma unroll
    for (int mt = 0; mt < 4; mt++) {
        int rl = mtile * BM + wm * 64 + mt * 16 + g;    // compacted row
        bool p0 = rl < nb, p1 = rl + 8 < nb;
        size_t base = ((size_t)(b * Odim + o) * Ldim + rl) * Hdim;
        #pragma unroll
        for (int nt = 0; nt < 4; nt++) {
            int j = jb + wn * 32 + nt * 8 + 2 * tig;
            if (p0)
                *reinterpret_cast<bf162*>(&g_U[base + j]) =
                    __floats2bfloat162_rn(acc[mt][nt][0], acc[mt][nt][1]);
            if (p1)
                *reinterpret_cast<bf162*>(&g_U[base + (size_t)8 * Hdim + j]) =
                    __floats2bfloat162_rn(acc[mt][nt][2], acc[mt][nt][3]);
        }
    }
}

// ------- GEMM 2 on compacted rows/cols, scatter epilogue ---------------------
__global__ __launch_bounds__(256) void gemm2_kernel(const float* __restrict__ w2,
                                                    float* __restrict__ out) {
    int z = blockIdx.z;
    int b = z / Odim, o = z - b * Odim;
    int nb = g_nb[b];
    if ((int)blockIdx.y * BM >= nb || (int)blockIdx.x * BN >= nb) return;

    __shared__ int   rowx[BM];
    __shared__ float rowv[BM];
    __shared__ int   coly[BN];
    __shared__ float colv[BN];

    const bf16* Ablk = g_U   + ((size_t)z * Ldim + blockIdx.y * BM) * Kdim;
    const bf16* Bblk = g_inc + ((size_t)b * Ldim + blockIdx.x * BN) * Kdim;
    float acc[4][4][4];
    #pragma unroll
    for (int i = 0; i < 4; i++)
        #pragma unroll
        for (int j = 0; j < 4; j++)
            #pragma unroll
            for (int e = 0; e < 4; e++) acc[i][j][e] = 0.f;
    gemm_mainloop(Ablk, Bblk, acc);

    int t = threadIdx.x, lane = t & 31, warp = t >> 5;
    int wm = warp >> 2, wn = warp & 3;
    int g = lane >> 2, tig = lane & 3;
    float bias = w2[2 * Hdim * Odim + o];
    if (t < BM) {
        int rg = blockIdx.y * BM + t;
        if (rg < nb) {
            int x = g_idx[b * Ldim + rg];
            rowx[t] = x;
            rowv[t] = g_lina[(b * Ldim + x) * Odim + o] + bias;
        } else rowx[t] = -1;
        int cg = blockIdx.x * BN + t;
        if (cg < nb) {
            int y = g_idx[b * Ldim + cg];
            coly[t] = y;
            colv[t] = g_linb[(b * Ldim + y) * Odim + o];
        } else coly[t] = -1;
    }
    __syncthreads();

    #pragma unroll
    for (int mt = 0; mt < 4; mt++) {
        #pragma unroll
        for (int h = 0; h < 2; h++) {
            int rl = wm * 64 + mt * 16 + g + h * 8;
            int x = rowx[rl];
            if (x < 0) continue;
            float rv = rowv[rl];
            float* orow = out + ((size_t)z * Ldim + x) * Ldim;
            #pragma unroll
            for (int nt = 0; nt < 4; nt++) {
                int cl = wn * 32 + nt * 8 + 2 * tig;
                int y0 = coly[cl], y1 = coly[cl + 1];
                float v0 = acc[mt][nt][h * 2]     + rv + colv[cl];
                float v1 = acc[mt][nt][h * 2 + 1] + rv + colv[cl + 1];
                if (y0 >= 0) orow[y0] = (y0 < x) ? v0 - NEGC : v0;
                if (y1 >= 0) orow[y1] = (y1 < x) ? v1 - NEGC : v1;
            }
        }
    }
}

// ---------------- launch ------------------------------------------------------
extern "C" void kernel_launch(void* const* d_in, const int* in_sizes, int n_in,
                              void* d_out, int out_size) {
    (void)out_size;
    const float* inputs = nullptr; const float* w1 = nullptr;
    const float* w2 = nullptr;     const int* mask = nullptr;
    for (int i = 0; i < n_in; i++) {
        int s = in_sizes[i];
        if      (s == Bdim * Ldim * Hdim)    inputs = (const float*)d_in[i];
        else if (s == Hdim * Odim * Hdim)    w1     = (const float*)d_in[i];
        else if (s == (2 * Hdim + 1) * Odim) w2     = (const float*)d_in[i];
        else if (s == Bdim * Ldim)           mask   = (const int*)d_in[i];
    }
    float* out = (float*)d_out;

    convert_in_kernel<<<(Bdim * Ldim * Hdim) / 1024, 256>>>(inputs);
    transpose_w1_kernel<<<dim3((Odim * Hdim) / 32, Hdim / 32), dim3(32, 8)>>>(w1);
    lin_kernel<<<Bdim * Ldim, 384>>>(inputs, w2);
    scan_kernel<<<Bdim, Ldim>>>(mask);
    compact_kernel<<<Bdim * Ldim, 128>>>();
    gemm1_kernel<<<dim3((Odim * Hdim) / BN, Bdim * 4), 256>>>();
    fill_kernel<<<(Bdim * Odim * Ldim * Ldim) / 1024, 256>>>(out);
    gemm2_kernel<<<dim3(4, 4, Bdim * Odim), 256>>>(w2, out);
}